// round 16
// baseline (speedup 1.0000x reference)
#include <cuda_runtime.h>
#include <cuda_fp16.h>
#include <math.h>
#include <stdint.h>

#define S_LEN 2048
#define BATCH 2
#define EMB   1024
#define NH    16
#define HD    64
#define HID   512
#define MROWS (S_LEN*BATCH)   // 4096
#define HSZ   (BATCH*NH*S_LEN*HD)
#define LOG2E 1.4426950408889634f

// ---------------- scratch (static device globals; no allocation) ----------
__device__ __align__(16) __half g_qkv[3*HSZ];      // q|k fp16 (B,H,S,D); v fp16 (B,H,D,S)
__device__ __align__(16) __half g_ctx[MROWS*EMB];  // (S,B,E) fp16
__device__ float  g_t1 [MROWS*HID];
__device__ float  g_mcomb[NH*HID];
__device__ float  g_cbias[NH];
__device__ float  g_mask[BATCH*NH*S_LEN];
__device__ __align__(16) __half g_qh  [MROWS*EMB]; // fp16 query
__device__ __align__(16) __half g_wqkv[3*EMB*EMB]; // fp16 q_w|k_w|v_w
__device__ __align__(16) __half g_wo  [EMB*EMB];   // fp16 out_w

// =================== helpers ===============================================
__device__ __forceinline__ uint32_t smem_u32(const void* p) {
    uint32_t a;
    asm("{ .reg .u64 t; cvta.to.shared.u64 t, %1; cvt.u32.u64 %0, t; }"
        : "=r"(a) : "l"(p));
    return a;
}
__device__ __forceinline__ void cp16(uint32_t saddr, const void* g) {
    asm volatile("cp.async.cg.shared.global [%0], [%1], 16;"
                 :: "r"(saddr), "l"(g) : "memory");
}
__device__ __forceinline__ void mma_f16(float* d, const uint32_t* a, const uint32_t* b) {
    asm volatile(
        "mma.sync.aligned.m16n8k16.row.col.f32.f16.f16.f32 "
        "{%0,%1,%2,%3}, {%4,%5,%6,%7}, {%8,%9}, {%0,%1,%2,%3};"
        : "+f"(d[0]), "+f"(d[1]), "+f"(d[2]), "+f"(d[3])
        : "r"(a[0]), "r"(a[1]), "r"(a[2]), "r"(a[3]), "r"(b[0]), "r"(b[1]));
}
__device__ __forceinline__ void ldsm4(uint32_t* r, uint32_t addr) {
    asm volatile("ldmatrix.sync.aligned.m8n8.x4.shared.b16 {%0,%1,%2,%3}, [%4];"
                 : "=r"(r[0]), "=r"(r[1]), "=r"(r[2]), "=r"(r[3]) : "r"(addr));
}
__device__ __forceinline__ uint32_t h2u(__half2 h) {
    return *(uint32_t*)&h;
}
// split fp16: x = hi + lo (hi,lo fp16), ~22-bit effective mantissa
__device__ __forceinline__ void split_h2(float x, float y, uint32_t& hi, uint32_t& lo) {
    __half hx = __float2half_rn(x), hy = __float2half_rn(y);
    __half lx = __float2half_rn(x - __half2float(hx));
    __half ly = __float2half_rn(y - __half2float(hy));
    hi = h2u(__halves2half2(hx, hy));
    lo = h2u(__halves2half2(lx, ly));
}

// ---------------- fp16 conversion kernels ----------------------------------
#define NQ4 (MROWS*EMB/4)      // 1048576
#define NW4 (EMB*EMB/4)        // 262144 = 1<<18
// main stream: query + q/k/v weights (needed before QKV gemm)
__global__ void round_main(const float* __restrict__ q,
                           const float* __restrict__ wq,
                           const float* __restrict__ wk,
                           const float* __restrict__ wv,
                           __half* __restrict__ dq,
                           __half* __restrict__ dwqkv)
{
    const int i = blockIdx.x * blockDim.x + threadIdx.x;
    const float4* src; __half* dst; int off;
    if (i < NQ4) { src = (const float4*)q; dst = dq; off = i; }
    else {
        const int j = i - NQ4;
        const int z = j >> 18;
        off = j & (NW4 - 1);
        if      (z == 0) { src = (const float4*)wq; dst = dwqkv; }
        else if (z == 1) { src = (const float4*)wk; dst = dwqkv + 4*NW4; }
        else             { src = (const float4*)wv; dst = dwqkv + 8*NW4; }
    }
    float4 v = src[off];
    __half2 lo = __floats2half2_rn(v.x, v.y);
    __half2 hi = __floats2half2_rn(v.z, v.w);
    uint2 pk = { h2u(lo), h2u(hi) };
    *(uint2*)(dst + (size_t)off * 4) = pk;
}
// side stream: out_w (only needed by hgemm_out, after flash)
__global__ void round_wo(const float* __restrict__ wo, __half* __restrict__ dwo)
{
    const int i = blockIdx.x * blockDim.x + threadIdx.x;
    if (i >= NW4) return;
    float4 v = ((const float4*)wo)[i];
    __half2 lo = __floats2half2_rn(v.x, v.y);
    __half2 hi = __floats2half2_rn(v.z, v.w);
    uint2 pk = { h2u(lo), h2u(hi) };
    *(uint2*)(dwo + (size_t)i * 4) = pk;
}

// =================== cp.async pipelined fp16 GEMM core =====================
// K-chunks of 64 halves; row pad 72 halves. Stage: A 9216 halves @0, W @9216;
// stage stride 18432 halves (36864 B). 2 stages = 73728 B.
#define HGEMM_BODY(Ag, Wg)                                                     \
    float acc[4][4][4];                                                        \
    _Pragma("unroll")                                                          \
    for (int i = 0; i < 4; i++)                                                \
        _Pragma("unroll")                                                      \
        for (int j = 0; j < 4; j++)                                            \
            _Pragma("unroll")                                                  \
            for (int f = 0; f < 4; f++) acc[i][j][f] = 0.f;                    \
    const int NC = K >> 6;                                                     \
    {                                                                          \
        const uint32_t ab = sbase, wb = sbase + 9216u * 2u;                    \
        _Pragma("unroll")                                                      \
        for (int i = 0; i < 4; i++) {                                          \
            const int fi = tid + i * 256;                                      \
            const int row = fi >> 3, seg = fi & 7;                             \
            const uint32_t off = (uint32_t)(row * 72 + seg * 8) * 2u;          \
            cp16(ab + off, Ag + (size_t)row * K + seg * 8);                    \
            cp16(wb + off, Wg + (size_t)row * K + seg * 8);                    \
        }                                                                      \
        asm volatile("cp.async.commit_group;" ::: "memory");                   \
    }                                                                          \
    for (int c = 0; c < NC; c++) {                                             \
        if (c + 1 < NC) {                                                      \
            const uint32_t st = (uint32_t)((c + 1) & 1) * 18432u * 2u;         \
            const uint32_t ab = sbase + st, wb = sbase + st + 9216u * 2u;      \
            const int kn = (c + 1) << 6;                                       \
            _Pragma("unroll")                                                  \
            for (int i = 0; i < 4; i++) {                                      \
                const int fi = tid + i * 256;                                  \
                const int row = fi >> 3, seg = fi & 7;                         \
                const uint32_t off = (uint32_t)(row * 72 + seg * 8) * 2u;      \
                cp16(ab + off, Ag + (size_t)row * K + kn + seg * 8);           \
                cp16(wb + off, Wg + (size_t)row * K + kn + seg * 8);           \
            }                                                                  \
            asm volatile("cp.async.commit_group;" ::: "memory");               \
            asm volatile("cp.async.wait_group 1;" ::: "memory");               \
        } else {                                                               \
            asm volatile("cp.async.wait_group 0;" ::: "memory");               \
        }                                                                      \
        __syncthreads();                                                       \
        const __half* As = swh + (c & 1) * 18432;                              \
        const __half* Ws = As + 9216;                                          \
        _Pragma("unroll")                                                      \
        for (int ks = 0; ks < 4; ks++) {                                       \
            const int k0 = ks * 16;                                            \
            uint32_t af[4][4];                                                 \
            _Pragma("unroll")                                                  \
            for (int mt = 0; mt < 4; mt++) {                                   \
                const int r = wm * 64 + mt * 16 + gid;                         \
                af[mt][0] = *(const uint32_t*)&As[ r      * 72 + k0 + 2*tig    ];\
                af[mt][1] = *(const uint32_t*)&As[(r + 8) * 72 + k0 + 2*tig    ];\
                af[mt][2] = *(const uint32_t*)&As[ r      * 72 + k0 + 2*tig + 8];\
                af[mt][3] = *(const uint32_t*)&As[(r + 8) * 72 + k0 + 2*tig + 8];\
            }                                                                  \
            uint32_t bf[4][2];                                                 \
            _Pragma("unroll")                                                  \
            for (int nt = 0; nt < 4; nt++) {                                   \
                const int n = wn * 32 + nt * 8 + gid;                          \
                bf[nt][0] = *(const uint32_t*)&Ws[n * 72 + k0 + 2*tig    ];    \
                bf[nt][1] = *(const uint32_t*)&Ws[n * 72 + k0 + 2*tig + 8];    \
            }                                                                  \
            _Pragma("unroll")                                                  \
            for (int mt = 0; mt < 4; mt++)                                     \
                _Pragma("unroll")                                              \
                for (int nt = 0; nt < 4; nt++)                                 \
                    mma_f16(acc[mt][nt], af[mt], bf[nt]);                      \
        }                                                                      \
        __syncthreads();                                                       \
    }

// ---- fused QKV projection: q/k -> (B,H,S,D) fp16; v -> (B,H,D,S) fp16 -----
__global__ __launch_bounds__(256, 2)
void hgemm_qkv(const __half* __restrict__ A, const __half* __restrict__ Wall,
               const float* __restrict__ bq, const float* __restrict__ bk,
               const float* __restrict__ bv, __half* __restrict__ Call, int K)
{
    extern __shared__ __align__(16) char smemraw[];
    __half* swh = (__half*)smemraw;
    const uint32_t sbase = smem_u32(swh);
    const int tid  = threadIdx.x;
    const int wid  = tid >> 5;
    const int lane = tid & 31;
    const int gid  = lane >> 2;
    const int tig  = lane & 3;
    const int wm   = wid >> 2;
    const int wn   = wid & 3;
    const int z    = blockIdx.z;

    const __half* Ag = A + (size_t)blockIdx.y * 128 * K;
    const __half* Wg = Wall + (size_t)z * EMB * EMB + (size_t)blockIdx.x * 128 * K;
    const float* bias = (z == 0) ? bq : (z == 1) ? bk : bv;
    __half* C = Call + (size_t)z * HSZ;
    const float scale = (z == 0) ? 0.125f * LOG2E : 1.f;

    HGEMM_BODY(Ag, Wg)

    if (z < 2) {
        #pragma unroll
        for (int mt = 0; mt < 4; mt++) {
            #pragma unroll
            for (int nt = 0; nt < 4; nt++) {
                const int n = blockIdx.x * 128 + wn * 32 + nt * 8 + tig * 2;
                const float b0 = bias[n], b1 = bias[n + 1];
                #pragma unroll
                for (int half_ = 0; half_ < 2; half_++) {
                    const int m = blockIdx.y * 128 + wm * 64 + mt * 16 + gid + half_ * 8;
                    const float vx = (acc[mt][nt][half_ * 2 + 0] + b0) * scale;
                    const float vy = (acc[mt][nt][half_ * 2 + 1] + b1) * scale;
                    const int s = m >> 1, b = m & 1;
                    const int h = n >> 6, d = n & 63;
                    __half2 hv = __floats2half2_rn(vx, vy);
                    *(uint32_t*)(C + (((size_t)(b * NH + h)) * S_LEN + s) * HD + d) = h2u(hv);
                }
            }
        }
    } else {
        __half* ts = swh;
        #pragma unroll
        for (int mt = 0; mt < 4; mt++) {
            #pragma unroll
            for (int nt = 0; nt < 4; nt++) {
                const int nl = wn * 32 + nt * 8 + tig * 2;
                const int n  = blockIdx.x * 128 + nl;
                const float b0 = bias[n], b1 = bias[n + 1];
                #pragma unroll
                for (int half_ = 0; half_ < 2; half_++) {
                    const int ml = wm * 64 + mt * 16 + gid + half_ * 8;
                    ts[ nl      * 136 + ml] = __float2half_rn(acc[mt][nt][half_ * 2 + 0] + b0);
                    ts[(nl + 1) * 136 + ml] = __float2half_rn(acc[mt][nt][half_ * 2 + 1] + b1);
                }
            }
        }
        __syncthreads();
        #pragma unroll 1
        for (int it = 0; it < 16; it++) {
            const int gr = it * 16 + wid * 2 + (lane >> 4);
            const int nl = gr >> 1, b = gr & 1;
            const int n  = blockIdx.x * 128 + nl;
            const int h  = n >> 6, d = n & 63;
            const int sl = (lane & 15) * 4;
            __half2 p0 = __halves2half2(ts[nl * 136 + 2 * (sl + 0) + b],
                                        ts[nl * 136 + 2 * (sl + 1) + b]);
            __half2 p1 = __halves2half2(ts[nl * 136 + 2 * (sl + 2) + b],
                                        ts[nl * 136 + 2 * (sl + 3) + b]);
            uint2 pk = { h2u(p0), h2u(p1) };
            const int s = blockIdx.y * 64 + sl;
            *(uint2*)(C + (((size_t)(b * NH + h)) * HD + d) * S_LEN + s) = pk;
        }
    }
}

// ---- output projection: ctx fp16 @ wo fp16 -> fp32 out --------------------
__global__ __launch_bounds__(256, 2)
void hgemm_out(const __half* __restrict__ A, const __half* __restrict__ W,
               const float* __restrict__ bias, float* __restrict__ C, int K)
{
    extern __shared__ __align__(16) char smemraw[];
    __half* swh = (__half*)smemraw;
    const uint32_t sbase = smem_u32(swh);
    const int tid  = threadIdx.x;
    const int wid  = tid >> 5;
    const int lane = tid & 31;
    const int gid  = lane >> 2;
    const int tig  = lane & 3;
    const int wm   = wid >> 2;
    const int wn   = wid & 3;

    const __half* Ag = A + (size_t)blockIdx.y * 128 * K;
    const __half* Wg = W + (size_t)blockIdx.x * 128 * K;

    HGEMM_BODY(Ag, Wg)

    #pragma unroll
    for (int mt = 0; mt < 4; mt++) {
        #pragma unroll
        for (int nt = 0; nt < 4; nt++) {
            const int n = blockIdx.x * 128 + wn * 32 + nt * 8 + tig * 2;
            const float b0 = bias[n], b1 = bias[n + 1];
            #pragma unroll
            for (int half_ = 0; half_ < 2; half_++) {
                const int m = blockIdx.y * 128 + wm * 64 + mt * 16 + gid + half_ * 8;
                float2 v;
                v.x = acc[mt][nt][half_ * 2 + 0] + b0;
                v.y = acc[mt][nt][half_ * 2 + 1] + b1;
                *(float2*)(C + (size_t)m * (gridDim.x * 128) + n) = v;
            }
        }
    }
}

// =================== split-fp16 (3xMMA k16) GEMM + ReLU for mask MLP =======
__global__ __launch_bounds__(256)
void hgemm_3x_relu(const float* __restrict__ A, const float* __restrict__ W,
                   const float* __restrict__ bias, float* __restrict__ C, int K)
{
    extern __shared__ __align__(16) char smemraw[];
    uint32_t* sw = (uint32_t*)smemraw;
    const uint32_t sbase = smem_u32(sw);
    const float* swf = (const float*)sw;
    const int tid  = threadIdx.x;
    const int wid  = tid >> 5;
    const int lane = tid & 31;
    const int gid  = lane >> 2;
    const int tig  = lane & 3;
    const int wm   = wid >> 2;
    const int wn   = wid & 3;

    const float* Ag = A + (size_t)blockIdx.y * 128 * K;
    const float* Wg = W + (size_t)blockIdx.x * 128 * K;

    float acc[4][4][4];
    #pragma unroll
    for (int i = 0; i < 4; i++)
        #pragma unroll
        for (int j = 0; j < 4; j++)
            #pragma unroll
            for (int f = 0; f < 4; f++) acc[i][j][f] = 0.f;

    const int NC = K >> 5;
    const int r0 = tid >> 3;
    const int sg = tid & 7;

    {
        const uint32_t ab = sbase, wb = sbase + 4608u * 4u;
        #pragma unroll
        for (int i = 0; i < 4; i++) {
            const int row = r0 + i * 32;
            const uint32_t off = (uint32_t)(row * 36 + sg * 4) * 4u;
            cp16(ab + off, Ag + (size_t)row * K + sg * 4);
            cp16(wb + off, Wg + (size_t)row * K + sg * 4);
        }
        asm volatile("cp.async.commit_group;" ::: "memory");
    }

    for (int c = 0; c < NC; c++) {
        if (c + 1 < NC) {
            const uint32_t st = (uint32_t)((c + 1) & 1) * 9216u * 4u;
            const uint32_t ab = sbase + st, wb = sbase + st + 4608u * 4u;
            const int kn = (c + 1) << 5;
            #pragma unroll
            for (int i = 0; i < 4; i++) {
                const int row = r0 + i * 32;
                const uint32_t off = (uint32_t)(row * 36 + sg * 4) * 4u;
                cp16(ab + off, Ag + (size_t)row * K + kn + sg * 4);
                cp16(wb + off, Wg + (size_t)row * K + kn + sg * 4);
            }
            asm volatile("cp.async.commit_group;" ::: "memory");
            asm volatile("cp.async.wait_group 1;" ::: "memory");
        } else {
            asm volatile("cp.async.wait_group 0;" ::: "memory");
        }
        __syncthreads();

        const float* As = swf + (c & 1) * 9216;
        const float* Ws = As + 4608;
        #pragma unroll
        for (int ks = 0; ks < 2; ks++) {
            const int k0 = ks * 16;
            uint32_t ah[4][4], al[4][4];
            #pragma unroll
            for (int mt = 0; mt < 4; mt++) {
                const int r = wm * 64 + mt * 16 + gid;
                float2 p0 = *(const float2*)&As[ r      * 36 + k0 + 2*tig    ];
                float2 p1 = *(const float2*)&As[(r + 8) * 36 + k0 + 2*tig    ];
                float2 p2 = *(const float2*)&As[ r      * 36 + k0 + 2*tig + 8];
                float2 p3 = *(const float2*)&As[(r + 8) * 36 + k0 + 2*tig + 8];
                split_h2(p0.x, p0.y, ah[mt][0], al[mt][0]);
                split_h2(p1.x, p1.y, ah[mt][1], al[mt][1]);
                split_h2(p2.x, p2.y, ah[mt][2], al[mt][2]);
                split_h2(p3.x, p3.y, ah[mt][3], al[mt][3]);
            }
            uint32_t bh_[4][2], bl_[4][2];
            #pragma unroll
            for (int nt = 0; nt < 4; nt++) {
                const int n = wn * 32 + nt * 8 + gid;
                float2 q0 = *(const float2*)&Ws[n * 36 + k0 + 2*tig    ];
                float2 q1 = *(const float2*)&Ws[n * 36 + k0 + 2*tig + 8];
                split_h2(q0.x, q0.y, bh_[nt][0], bl_[nt][0]);
                split_h2(q1.x, q1.y, bh_[nt][1], bl_[nt][1]);
            }
            #pragma unroll
            for (int mt = 0; mt < 4; mt++)
                #pragma unroll
                for (int nt = 0; nt < 4; nt++) {
                    mma_f16(acc[mt][nt], al[mt], bh_[nt]);
                    mma_f16(acc[mt][nt], ah[mt], bl_[nt]);
                    mma_f16(acc[mt][nt], ah[mt], bh_[nt]);
                }
        }
        __syncthreads();
    }

    #pragma unroll
    for (int mt = 0; mt < 4; mt++) {
        #pragma unroll
        for (int nt = 0; nt < 4; nt++) {
            const int n = blockIdx.x * 128 + wn * 32 + nt * 8 + tig * 2;
            const float b0 = bias[n], b1 = bias[n + 1];
            #pragma unroll
            for (int half_ = 0; half_ < 2; half_++) {
                const int m = blockIdx.y * 128 + wm * 64 + mt * 16 + gid + half_ * 8;
                float2 v;
                v.x = fmaxf(acc[mt][nt][half_ * 2 + 0] + b0, 0.f);
                v.y = fmaxf(acc[mt][nt][half_ * 2 + 1] + b1, 0.f);
                *(float2*)(C + (size_t)m * (gridDim.x * 128) + n) = v;
            }
        }
    }
}

// =================== fp16 flash attention: 3-stage ring, 1 barrier/iter ====
// Q,K fp16 (B,H,S,D); V fp16 transposed (B,H,D,S). exp2 softmax.
// smem: 3 stages x (K 64x72 + Vt 64x72 halves) = 55296 B.
__global__ __launch_bounds__(256, 2)
void flash_h(const __half* __restrict__ Q, const __half* __restrict__ Kg,
             const __half* __restrict__ Vg, const float* __restrict__ gate,
             __half* __restrict__ ctx)
{
    extern __shared__ __align__(16) char smemraw[];
    __half* swh = (__half*)smemraw;
    const uint32_t sbase = smem_u32(swh);
    const int tid  = threadIdx.x;
    const int wid  = tid >> 5;
    const int lane = tid & 31;
    const int gid  = lane >> 2;
    const int tig  = lane & 3;
    const int bh   = blockIdx.y;
    const int b    = bh >> 4, h = bh & 15;
    const int q0   = blockIdx.x * 128;

    const __half* Qt = Q  + ((size_t)bh * S_LEN + q0) * HD;
    const __half* Kb = Kg + (size_t)bh * S_LEN * HD;
    const __half* Vb = Vg + (size_t)bh * HD * S_LEN;

    const int a23 = lane >> 3, rin = lane & 7;
    const uint32_t alane = (uint32_t)((((a23 & 1) * 8 + rin) * 72 + (a23 >> 1) * 8) * 2);
    const uint32_t blane = (uint32_t)((((a23 >> 1) * 8 + rin) * 72 + (a23 & 1) * 8) * 2);

    // ---- stage Q then ldmatrix the A fragments -----------------------------
    #pragma unroll
    for (int i = 0; i < 4; i++) {
        const int fi = tid + i * 256;
        const int r = fi >> 3, seg = fi & 7;
        uint4 v = *(const uint4*)(Qt + r * 64 + seg * 8);
        *(uint4*)(swh + r * 72 + seg * 8) = v;
    }
    __syncthreads();
    uint32_t qa[4][4];
    {
        const uint32_t qaddr = sbase + (uint32_t)(wid * 16) * 144u + alane;
        #pragma unroll
        for (int ks = 0; ks < 4; ks++)
            ldsm4(qa[ks], qaddr + (uint32_t)(ks * 32));
    }
    __syncthreads();

    // ---- issue first two K/V tiles into stages 0,1 -------------------------
    #pragma unroll 1
    for (int t = 0; t < 2; t++) {
        const uint32_t kb = sbase + (uint32_t)t * 18432u;
        const uint32_t vb = kb + 9216u;
        const __half* Ksrc = Kb + (size_t)t * 64 * 64;
        const __half* Vsrc = Vb + (size_t)t * 64;
        #pragma unroll
        for (int i = 0; i < 4; i++) {
            const int fi = tid + i * 256;
            const int half_sel = fi >> 9;
            const int j = fi & 511;
            const int r = j >> 3, seg = j & 7;
            if (half_sel == 0)
                cp16(kb + (uint32_t)(r * 72 + seg * 8) * 2u, Ksrc + r * 64 + seg * 8);
            else
                cp16(vb + (uint32_t)(r * 72 + seg * 8) * 2u, Vsrc + (size_t)r * S_LEN + seg * 8);
        }
        asm volatile("cp.async.commit_group;" ::: "memory");
    }

    float miA = -INFINITY, miB = -INFINITY, liA = 0.f, liB = 0.f;
    float oa[8][4];
    #pragma unroll
    for (int nt = 0; nt < 8; nt++)
        #pragma unroll
        for (int f = 0; f < 4; f++) oa[nt][f] = 0.f;

    const int NT = S_LEN / 64;
    int st = 0, pst = 2;                 // consume stage, prefetch stage (mod 3)
    for (int t = 0; t < NT; t++) {
        // tile t's copies complete (in flight: t, t+1)
        if (t + 1 < NT) asm volatile("cp.async.wait_group 1;" ::: "memory");
        else            asm volatile("cp.async.wait_group 0;" ::: "memory");
        // single barrier: publishes tile t CTA-wide AND proves all warps done
        // with stage pst (consumed at iter t-1) before its refill below
        __syncthreads();
        if (t + 2 < NT) {
            const uint32_t kb = sbase + (uint32_t)pst * 18432u;
            const uint32_t vb = kb + 9216u;
            const __half* Ksrc = Kb + (size_t)(t + 2) * 64 * 64;
            const __half* Vsrc = Vb + (size_t)(t + 2) * 64;
            #pragma unroll
            for (int i = 0; i < 4; i++) {
                const int fi = tid + i * 256;
                const int half_sel = fi >> 9;
                const int j = fi & 511;
                const int r = j >> 3, seg = j & 7;
                if (half_sel == 0)
                    cp16(kb + (uint32_t)(r * 72 + seg * 8) * 2u, Ksrc + r * 64 + seg * 8);
                else
                    cp16(vb + (uint32_t)(r * 72 + seg * 8) * 2u, Vsrc + (size_t)r * S_LEN + seg * 8);
            }
            asm volatile("cp.async.commit_group;" ::: "memory");
        }
        const uint32_t ksAddr = sbase + (uint32_t)st * 18432u + blane;
        const uint32_t vsAddr = ksAddr + 9216u;

        // ---- S = Q K^T -----------------------------------------------------
        float sa[8][4];
        #pragma unroll
        for (int nt = 0; nt < 8; nt++)
            #pragma unroll
            for (int f = 0; f < 4; f++) sa[nt][f] = 0.f;
        #pragma unroll
        for (int ks = 0; ks < 4; ks++) {
            #pragma unroll
            for (int ntp = 0; ntp < 4; ntp++) {
                uint32_t b4[4];
                ldsm4(b4, ksAddr + (uint32_t)(ntp * 2304 + ks * 32));
                mma_f16(sa[2*ntp    ], qa[ks], &b4[0]);
                mma_f16(sa[2*ntp + 1], qa[ks], &b4[2]);
            }
        }

        // ---- online softmax (exp2 domain) ----------------------------------
        float rmA = -INFINITY, rmB = -INFINITY;
        #pragma unroll
        for (int nt = 0; nt < 8; nt++) {
            rmA = fmaxf(rmA, fmaxf(sa[nt][0], sa[nt][1]));
            rmB = fmaxf(rmB, fmaxf(sa[nt][2], sa[nt][3]));
        }
        rmA = fmaxf(rmA, __shfl_xor_sync(0xffffffffu, rmA, 1));
        rmA = fmaxf(rmA, __shfl_xor_sync(0xffffffffu, rmA, 2));
        rmB = fmaxf(rmB, __shfl_xor_sync(0xffffffffu, rmB, 1));
        rmB = fmaxf(rmB, __shfl_xor_sync(0xffffffffu, rmB, 2));

        const float mAn = fmaxf(miA, rmA);
        const float mBn = fmaxf(miB, rmB);
        const float aA  = exp2f(miA - mAn);
        const float aB  = exp2f(miB - mBn);
        miA = mAn; miB = mBn;

        float rsA = 0.f, rsB = 0.f;
        #pragma unroll
        for (int nt = 0; nt < 8; nt++) {
            sa[nt][0] = exp2f(sa[nt][0] - mAn);
            sa[nt][1] = exp2f(sa[nt][1] - mAn);
            sa[nt][2] = exp2f(sa[nt][2] - mBn);
            sa[nt][3] = exp2f(sa[nt][3] - mBn);
            rsA += sa[nt][0] + sa[nt][1];
            rsB += sa[nt][2] + sa[nt][3];
        }
        rsA += __shfl_xor_sync(0xffffffffu, rsA, 1);
        rsA += __shfl_xor_sync(0xffffffffu, rsA, 2);
        rsB += __shfl_xor_sync(0xffffffffu, rsB, 1);
        rsB += __shfl_xor_sync(0xffffffffu, rsB, 2);
        liA = liA * aA + rsA;
        liB = liB * aB + rsB;
        #pragma unroll
        for (int nt = 0; nt < 8; nt++) {
            oa[nt][0] *= aA; oa[nt][1] *= aA;
            oa[nt][2] *= aB; oa[nt][3] *= aB;
        }

        // ---- O += P V ------------------------------------------------------
        #pragma unroll
        for (int kk = 0; kk < 4; kk++) {
            uint32_t af[4];
            af[0] = h2u(__floats2half2_rn(sa[2*kk  ][0], sa[2*kk  ][1]));
            af[1] = h2u(__floats2half2_rn(sa[2*kk  ][2], sa[2*kk  ][3]));
            af[2] = h2u(__floats2half2_rn(sa[2*kk+1][0], sa[2*kk+1][1]));
            af[3] = h2u(__floats2half2_rn(sa[2*kk+1][2], sa[2*kk+1][3]));
            #pragma unroll
            for (int ntp = 0; ntp < 4; ntp++) {
                uint32_t b4[4];
                ldsm4(b4, vsAddr + (uint32_t)(ntp * 2304 + kk * 32));
                mma_f16(oa[2*ntp    ], af, &b4[0]);
                mma_f16(oa[2*ntp + 1], af, &b4[2]);
            }
        }

        st  = (st  == 2) ? 0 : st  + 1;
        pst = (pst == 2) ? 0 : pst + 1;
    }

    // ---- epilogue ----------------------------------------------------------
    const int sA = q0 + wid * 16 + gid;
    const int sB = sA + 8;
    const float gA = gate[(size_t)bh * S_LEN + sA];
    const float gB = gate[(size_t)bh * S_LEN + sB];
    const float invA = gA / liA;
    const float invB = gB / liB;
    #pragma unroll
    for (int nt = 0; nt < 8; nt++) {
        const int col = h * 64 + nt * 8 + tig * 2;
        __half2 va = __floats2half2_rn(oa[nt][0] * invA, oa[nt][1] * invA);
        __half2 vb = __floats2half2_rn(oa[nt][2] * invB, oa[nt][3] * invB);
        *(uint32_t*)(ctx + ((size_t)sA * BATCH + b) * EMB + col) = h2u(va);
        *(uint32_t*)(ctx + ((size_t)sB * BATCH + b) * EMB + col) = h2u(vb);
    }
}

// ---------------- fold head_sig into inf2 ---------------------------------
__global__ void combine_sig(const float* __restrict__ hs,
                            const float* __restrict__ w2,
                            const float* __restrict__ b2,
                            float* __restrict__ mcomb,
                            float* __restrict__ cbias)
{
    const int idx = blockIdx.x * blockDim.x + threadIdx.x;
    if (idx < NH * HID) {
        const int h = idx / HID, k = idx % HID;
        float a = 0.f;
        #pragma unroll
        for (int j = 0; j < 64; j++) a += hs[h*64 + j] * w2[j*HID + k];
        mcomb[idx] = a;
    }
    if (idx < NH) {
        float a = 0.f;
        #pragma unroll
        for (int j = 0; j < 64; j++) a += hs[idx*64 + j] * b2[j];
        cbias[idx] = a;
    }
}

// ---------------- head scores + top-12 mask (float4 loads) ----------------
__global__ __launch_bounds__(256)
void head_scores(const float* __restrict__ t1, const float* __restrict__ mcomb,
                 const float* __restrict__ cbias, float* __restrict__ mask)
{
    const int warp = (blockIdx.x * blockDim.x + threadIdx.x) >> 5;
    const int lane = threadIdx.x & 31;
    if (warp >= MROWS) return;
    const float4* row4 = (const float4*)(t1 + (size_t)warp * HID);
    const float4* mc4  = (const float4*)mcomb;

    float acc[NH];
    #pragma unroll
    for (int h = 0; h < NH; h++) acc[h] = 0.f;
    #pragma unroll
    for (int it = 0; it < 4; it++) {
        const int k4 = it * 32 + lane;
        const float4 a = row4[k4];
        #pragma unroll
        for (int h = 0; h < NH; h++) {
            const float4 m = mc4[h * (HID/4) + k4];
            acc[h] += a.x*m.x + a.y*m.y + a.z*m.z + a.w*m.w;
        }
    }
    #pragma unroll
    for (int h = 0; h < NH; h++)
        #pragma unroll
        for (int off = 16; off > 0; off >>= 1)
            acc[h] += __shfl_xor_sync(0xffffffffu, acc[h], off);

    if (lane == 0) {
        float sc[NH], tmp[NH];
        #pragma unroll
        for (int h = 0; h < NH; h++) { sc[h] = acc[h] + cbias[h]; tmp[h] = sc[h]; }
        float thr = 0.f;
        for (int it = 0; it < NH - 4; it++) {
            int bi = 0; float bv = tmp[0];
            #pragma unroll
            for (int h = 1; h < NH; h++) if (tmp[h] > bv) { bv = tmp[h]; bi = h; }
            thr = bv; tmp[bi] = -INFINITY;
        }
        const int s = warp >> 1, b = warp & 1;
        #pragma unroll
        for (int h = 0; h < NH; h++)
            mask[((size_t)(b * NH + h)) * S_LEN + s] = (sc[h] >= thr) ? 1.f : 0.f;
    }
}

// ---------------------------------------------------------------------------
extern "C" void kernel_launch(void* const* d_in, const int* in_sizes, int n_in,
                              void* d_out, int out_size)
{
    const float* query   = (const float*)d_in[0];
    const float* q_w     = (const float*)d_in[1];
    const float* q_b     = (const float*)d_in[2];
    const float* k_w     = (const float*)d_in[3];
    const float* k_b     = (const float*)d_in[4];
    const float* v_w     = (const float*)d_in[5];
    const float* v_b     = (const float*)d_in[6];
    const float* out_w   = (const float*)d_in[7];
    const float* out_b   = (const float*)d_in[8];
    const float* inf1_w  = (const float*)d_in[9];
    const float* inf1_b  = (const float*)d_in[10];
    const float* inf2_w  = (const float*)d_in[11];
    const float* inf2_b  = (const float*)d_in[12];
    const float* head_sig= (const float*)d_in[13];
    float* out = (float*)d_out;

    __half *pqkv, *pctx, *pqh, *pwqkv, *pwo;
    float *pt1, *pmc, *pcb, *pmask;
    cudaGetSymbolAddress((void**)&pqkv, g_qkv);
    cudaGetSymbolAddress((void**)&pctx, g_ctx);
    cudaGetSymbolAddress((void**)&pt1,  g_t1);
    cudaGetSymbolAddress((void**)&pmc,  g_mcomb);
    cudaGetSymbolAddress((void**)&pcb,  g_cbias);
    cudaGetSymbolAddress((void**)&pmask,g_mask);
    cudaGetSymbolAddress((void**)&pqh,  g_qh);
    cudaGetSymbolAddress((void**)&pwqkv,g_wqkv);
    cudaGetSymbolAddress((void**)&pwo,  g_wo);

    const int HGS = 73728;   // fp16 GEMM: 2 stages x 18432 halves
    const int GS3 = 73728;   // mask MLP fp32 stage layout
    const int FS  = 55296;   // flash fp16: 3 stages x 18432 B
    cudaFuncSetAttribute(hgemm_qkv, cudaFuncAttributeMaxDynamicSharedMemorySize, HGS);
    cudaFuncSetAttribute(hgemm_out, cudaFuncAttributeMaxDynamicSharedMemorySize, HGS);
    cudaFuncSetAttribute(hgemm_3x_relu, cudaFuncAttributeMaxDynamicSharedMemorySize, GS3);
    cudaFuncSetAttribute(flash_h, cudaFuncAttributeMaxDynamicSharedMemorySize, FS);

    // side stream + fork/join events (created per call; never destroyed so
    // the captured graph's references stay valid)
    cudaStream_t s2;
    cudaEvent_t eFork, eJoin;
    cudaStreamCreateWithFlags(&s2, cudaStreamNonBlocking);
    cudaEventCreateWithFlags(&eFork, cudaEventDisableTiming);
    cudaEventCreateWithFlags(&eJoin, cudaEventDisableTiming);

    cudaEventRecord(eFork, 0);
    cudaStreamWaitEvent(s2, eFork, 0);

    // --- side stream: wo convert -> combine_sig -> MLP -> head_scores ------
    round_wo<<<(NW4 + 255)/256, 256, 0, s2>>>(out_w, pwo);
    combine_sig<<<(NH*HID + 255)/256, 256, 0, s2>>>(head_sig, inf2_w, inf2_b,
                                                    pmc, pcb);
    {
        dim3 g(HID/128, MROWS/128);
        hgemm_3x_relu<<<g, 256, GS3, s2>>>(query, inf1_w, inf1_b, pt1, EMB);
    }
    head_scores<<<MROWS/8, 256, 0, s2>>>(pt1, pmc, pcb, pmask);
    cudaEventRecord(eJoin, s2);

    // --- main stream: fp16 convert (query + qkv weights) -> QKV -------------
    {
        const int total = NQ4 + 3 * NW4;
        round_main<<<(total + 255)/256, 256>>>(query, q_w, k_w, v_w, pqh, pwqkv);
    }
    {
        dim3 g(EMB/128, MROWS/128, 3);
        hgemm_qkv<<<g, 256, HGS>>>(pqh, pwqkv, q_b, k_b, v_b, pqkv, EMB);
    }

    cudaStreamWaitEvent(0, eJoin, 0);

    // --- flash attention (fp16, ldmatrix, 3-stage) -> ctx fp16 --------------
    {
        dim3 g(S_LEN/128, BATCH*NH);
        flash_h<<<g, 256, FS>>>(pqkv, pqkv + HSZ, pqkv + 2*HSZ, pmask, pctx);
    }
    // --- output projection ---------------------------------------------------
    {
        dim3 g(EMB/128, MROWS/128);
        hgemm_out<<<g, 256, HGS>>>(pctx, pwo, out_b, out, EMB);
    }
    (void)in_sizes; (void)n_in; (void)out_size;
}

// round 17
// speedup vs baseline: 1.0164x; 1.0164x over previous
#include <cuda_runtime.h>
#include <cuda_fp16.h>
#include <math.h>
#include <stdint.h>

#define S_LEN 2048
#define BATCH 2
#define EMB   1024
#define NH    16
#define HD    64
#define HID   512
#define MROWS (S_LEN*BATCH)   // 4096
#define HSZ   (BATCH*NH*S_LEN*HD)
#define LOG2E 1.4426950408889634f

// ---------------- scratch (static device globals; no allocation) ----------
__device__ __align__(16) __half g_qkv[3*HSZ];      // q|k fp16 (B,H,S,D); v fp16 (B,H,D,S)
__device__ __align__(16) __half g_ctx[MROWS*EMB];  // (S,B,E) fp16
__device__ float  g_t1 [MROWS*HID];
__device__ float  g_mcomb[NH*HID];
__device__ float  g_cbias[NH];
__device__ float  g_mask[BATCH*NH*S_LEN];
__device__ __align__(16) __half g_qh  [MROWS*EMB]; // fp16 query
__device__ __align__(16) __half g_wqkv[3*EMB*EMB]; // fp16 q_w|k_w|v_w
__device__ __align__(16) __half g_wo  [EMB*EMB];   // fp16 out_w

// =================== helpers ===============================================
__device__ __forceinline__ uint32_t smem_u32(const void* p) {
    uint32_t a;
    asm("{ .reg .u64 t; cvta.to.shared.u64 t, %1; cvt.u32.u64 %0, t; }"
        : "=r"(a) : "l"(p));
    return a;
}
__device__ __forceinline__ void cp16(uint32_t saddr, const void* g) {
    asm volatile("cp.async.cg.shared.global [%0], [%1], 16;"
                 :: "r"(saddr), "l"(g) : "memory");
}
__device__ __forceinline__ void mma_f16(float* d, const uint32_t* a, const uint32_t* b) {
    asm volatile(
        "mma.sync.aligned.m16n8k16.row.col.f32.f16.f16.f32 "
        "{%0,%1,%2,%3}, {%4,%5,%6,%7}, {%8,%9}, {%0,%1,%2,%3};"
        : "+f"(d[0]), "+f"(d[1]), "+f"(d[2]), "+f"(d[3])
        : "r"(a[0]), "r"(a[1]), "r"(a[2]), "r"(a[3]), "r"(b[0]), "r"(b[1]));
}
__device__ __forceinline__ void ldsm4(uint32_t* r, uint32_t addr) {
    asm volatile("ldmatrix.sync.aligned.m8n8.x4.shared.b16 {%0,%1,%2,%3}, [%4];"
                 : "=r"(r[0]), "=r"(r[1]), "=r"(r[2]), "=r"(r[3]) : "r"(addr));
}
__device__ __forceinline__ uint32_t h2u(__half2 h) {
    return *(uint32_t*)&h;
}
// split fp16: x = hi + lo (hi,lo fp16), ~22-bit effective mantissa
__device__ __forceinline__ void split_h2(float x, float y, uint32_t& hi, uint32_t& lo) {
    __half hx = __float2half_rn(x), hy = __float2half_rn(y);
    __half lx = __float2half_rn(x - __half2float(hx));
    __half ly = __float2half_rn(y - __half2float(hy));
    hi = h2u(__halves2half2(hx, hy));
    lo = h2u(__halves2half2(lx, ly));
}

// ---------------- fp16 conversion kernels ----------------------------------
#define NQ4 (MROWS*EMB/4)      // 1048576
#define NW4 (EMB*EMB/4)        // 262144 = 1<<18
// main stream: query + q/k/v weights (needed before QKV gemm)
__global__ void round_main(const float* __restrict__ q,
                           const float* __restrict__ wq,
                           const float* __restrict__ wk,
                           const float* __restrict__ wv,
                           __half* __restrict__ dq,
                           __half* __restrict__ dwqkv)
{
    const int i = blockIdx.x * blockDim.x + threadIdx.x;
    const float4* src; __half* dst; int off;
    if (i < NQ4) { src = (const float4*)q; dst = dq; off = i; }
    else {
        const int j = i - NQ4;
        const int z = j >> 18;
        off = j & (NW4 - 1);
        if      (z == 0) { src = (const float4*)wq; dst = dwqkv; }
        else if (z == 1) { src = (const float4*)wk; dst = dwqkv + 4*NW4; }
        else             { src = (const float4*)wv; dst = dwqkv + 8*NW4; }
    }
    float4 v = src[off];
    __half2 lo = __floats2half2_rn(v.x, v.y);
    __half2 hi = __floats2half2_rn(v.z, v.w);
    uint2 pk = { h2u(lo), h2u(hi) };
    *(uint2*)(dst + (size_t)off * 4) = pk;
}
// side stream: out_w (only needed by hgemm_out, after flash)
__global__ void round_wo(const float* __restrict__ wo, __half* __restrict__ dwo)
{
    const int i = blockIdx.x * blockDim.x + threadIdx.x;
    if (i >= NW4) return;
    float4 v = ((const float4*)wo)[i];
    __half2 lo = __floats2half2_rn(v.x, v.y);
    __half2 hi = __floats2half2_rn(v.z, v.w);
    uint2 pk = { h2u(lo), h2u(hi) };
    *(uint2*)(dwo + (size_t)i * 4) = pk;
}

// =================== cp.async pipelined fp16 GEMM core =====================
// K-chunks of 64 halves; row pad 72 halves. Stage: A 9216 halves @0, W @9216;
// stage stride 18432 halves (36864 B). 2 stages = 73728 B.
#define HGEMM_BODY(Ag, Wg)                                                     \
    float acc[4][4][4];                                                        \
    _Pragma("unroll")                                                          \
    for (int i = 0; i < 4; i++)                                                \
        _Pragma("unroll")                                                      \
        for (int j = 0; j < 4; j++)                                            \
            _Pragma("unroll")                                                  \
            for (int f = 0; f < 4; f++) acc[i][j][f] = 0.f;                    \
    const int NC = K >> 6;                                                     \
    {                                                                          \
        const uint32_t ab = sbase, wb = sbase + 9216u * 2u;                    \
        _Pragma("unroll")                                                      \
        for (int i = 0; i < 4; i++) {                                          \
            const int fi = tid + i * 256;                                      \
            const int row = fi >> 3, seg = fi & 7;                             \
            const uint32_t off = (uint32_t)(row * 72 + seg * 8) * 2u;          \
            cp16(ab + off, Ag + (size_t)row * K + seg * 8);                    \
            cp16(wb + off, Wg + (size_t)row * K + seg * 8);                    \
        }                                                                      \
        asm volatile("cp.async.commit_group;" ::: "memory");                   \
    }                                                                          \
    for (int c = 0; c < NC; c++) {                                             \
        if (c + 1 < NC) {                                                      \
            const uint32_t st = (uint32_t)((c + 1) & 1) * 18432u * 2u;         \
            const uint32_t ab = sbase + st, wb = sbase + st + 9216u * 2u;      \
            const int kn = (c + 1) << 6;                                       \
            _Pragma("unroll")                                                  \
            for (int i = 0; i < 4; i++) {                                      \
                const int fi = tid + i * 256;                                  \
                const int row = fi >> 3, seg = fi & 7;                         \
                const uint32_t off = (uint32_t)(row * 72 + seg * 8) * 2u;      \
                cp16(ab + off, Ag + (size_t)row * K + kn + seg * 8);           \
                cp16(wb + off, Wg + (size_t)row * K + kn + seg * 8);           \
            }                                                                  \
            asm volatile("cp.async.commit_group;" ::: "memory");               \
            asm volatile("cp.async.wait_group 1;" ::: "memory");               \
        } else {                                                               \
            asm volatile("cp.async.wait_group 0;" ::: "memory");               \
        }                                                                      \
        __syncthreads();                                                       \
        const __half* As = swh + (c & 1) * 18432;                              \
        const __half* Ws = As + 9216;                                          \
        _Pragma("unroll")                                                      \
        for (int ks = 0; ks < 4; ks++) {                                       \
            const int k0 = ks * 16;                                            \
            uint32_t af[4][4];                                                 \
            _Pragma("unroll")                                                  \
            for (int mt = 0; mt < 4; mt++) {                                   \
                const int r = wm * 64 + mt * 16 + gid;                         \
                af[mt][0] = *(const uint32_t*)&As[ r      * 72 + k0 + 2*tig    ];\
                af[mt][1] = *(const uint32_t*)&As[(r + 8) * 72 + k0 + 2*tig    ];\
                af[mt][2] = *(const uint32_t*)&As[ r      * 72 + k0 + 2*tig + 8];\
                af[mt][3] = *(const uint32_t*)&As[(r + 8) * 72 + k0 + 2*tig + 8];\
            }                                                                  \
            uint32_t bf[4][2];                                                 \
            _Pragma("unroll")                                                  \
            for (int nt = 0; nt < 4; nt++) {                                   \
                const int n = wn * 32 + nt * 8 + gid;                          \
                bf[nt][0] = *(const uint32_t*)&Ws[n * 72 + k0 + 2*tig    ];    \
                bf[nt][1] = *(const uint32_t*)&Ws[n * 72 + k0 + 2*tig + 8];    \
            }                                                                  \
            _Pragma("unroll")                                                  \
            for (int mt = 0; mt < 4; mt++)                                     \
                _Pragma("unroll")                                              \
                for (int nt = 0; nt < 4; nt++)                                 \
                    mma_f16(acc[mt][nt], af[mt], bf[nt]);                      \
        }                                                                      \
        __syncthreads();                                                       \
    }

// ---- fused QKV projection: q/k -> (B,H,S,D) fp16; v -> (B,H,D,S) fp16 -----
__global__ __launch_bounds__(256, 2)
void hgemm_qkv(const __half* __restrict__ A, const __half* __restrict__ Wall,
               const float* __restrict__ bq, const float* __restrict__ bk,
               const float* __restrict__ bv, __half* __restrict__ Call, int K)
{
    extern __shared__ __align__(16) char smemraw[];
    __half* swh = (__half*)smemraw;
    const uint32_t sbase = smem_u32(swh);
    const int tid  = threadIdx.x;
    const int wid  = tid >> 5;
    const int lane = tid & 31;
    const int gid  = lane >> 2;
    const int tig  = lane & 3;
    const int wm   = wid >> 2;
    const int wn   = wid & 3;
    const int z    = blockIdx.z;

    const __half* Ag = A + (size_t)blockIdx.y * 128 * K;
    const __half* Wg = Wall + (size_t)z * EMB * EMB + (size_t)blockIdx.x * 128 * K;
    const float* bias = (z == 0) ? bq : (z == 1) ? bk : bv;
    __half* C = Call + (size_t)z * HSZ;
    const float scale = (z == 0) ? 0.125f * LOG2E : 1.f;

    HGEMM_BODY(Ag, Wg)

    if (z < 2) {
        #pragma unroll
        for (int mt = 0; mt < 4; mt++) {
            #pragma unroll
            for (int nt = 0; nt < 4; nt++) {
                const int n = blockIdx.x * 128 + wn * 32 + nt * 8 + tig * 2;
                const float b0 = bias[n], b1 = bias[n + 1];
                #pragma unroll
                for (int half_ = 0; half_ < 2; half_++) {
                    const int m = blockIdx.y * 128 + wm * 64 + mt * 16 + gid + half_ * 8;
                    const float vx = (acc[mt][nt][half_ * 2 + 0] + b0) * scale;
                    const float vy = (acc[mt][nt][half_ * 2 + 1] + b1) * scale;
                    const int s = m >> 1, b = m & 1;
                    const int h = n >> 6, d = n & 63;
                    __half2 hv = __floats2half2_rn(vx, vy);
                    *(uint32_t*)(C + (((size_t)(b * NH + h)) * S_LEN + s) * HD + d) = h2u(hv);
                }
            }
        }
    } else {
        __half* ts = swh;
        #pragma unroll
        for (int mt = 0; mt < 4; mt++) {
            #pragma unroll
            for (int nt = 0; nt < 4; nt++) {
                const int nl = wn * 32 + nt * 8 + tig * 2;
                const int n  = blockIdx.x * 128 + nl;
                const float b0 = bias[n], b1 = bias[n + 1];
                #pragma unroll
                for (int half_ = 0; half_ < 2; half_++) {
                    const int ml = wm * 64 + mt * 16 + gid + half_ * 8;
                    ts[ nl      * 136 + ml] = __float2half_rn(acc[mt][nt][half_ * 2 + 0] + b0);
                    ts[(nl + 1) * 136 + ml] = __float2half_rn(acc[mt][nt][half_ * 2 + 1] + b1);
                }
            }
        }
        __syncthreads();
        #pragma unroll 1
        for (int it = 0; it < 16; it++) {
            const int gr = it * 16 + wid * 2 + (lane >> 4);
            const int nl = gr >> 1, b = gr & 1;
            const int n  = blockIdx.x * 128 + nl;
            const int h  = n >> 6, d = n & 63;
            const int sl = (lane & 15) * 4;
            __half2 p0 = __halves2half2(ts[nl * 136 + 2 * (sl + 0) + b],
                                        ts[nl * 136 + 2 * (sl + 1) + b]);
            __half2 p1 = __halves2half2(ts[nl * 136 + 2 * (sl + 2) + b],
                                        ts[nl * 136 + 2 * (sl + 3) + b]);
            uint2 pk = { h2u(p0), h2u(p1) };
            const int s = blockIdx.y * 64 + sl;
            *(uint2*)(C + (((size_t)(b * NH + h)) * HD + d) * S_LEN + s) = pk;
        }
    }
}

// ---- output projection: ctx fp16 @ wo fp16 -> fp32 out --------------------
__global__ __launch_bounds__(256, 2)
void hgemm_out(const __half* __restrict__ A, const __half* __restrict__ W,
               const float* __restrict__ bias, float* __restrict__ C, int K)
{
    extern __shared__ __align__(16) char smemraw[];
    __half* swh = (__half*)smemraw;
    const uint32_t sbase = smem_u32(swh);
    const int tid  = threadIdx.x;
    const int wid  = tid >> 5;
    const int lane = tid & 31;
    const int gid  = lane >> 2;
    const int tig  = lane & 3;
    const int wm   = wid >> 2;
    const int wn   = wid & 3;

    const __half* Ag = A + (size_t)blockIdx.y * 128 * K;
    const __half* Wg = W + (size_t)blockIdx.x * 128 * K;

    HGEMM_BODY(Ag, Wg)

    #pragma unroll
    for (int mt = 0; mt < 4; mt++) {
        #pragma unroll
        for (int nt = 0; nt < 4; nt++) {
            const int n = blockIdx.x * 128 + wn * 32 + nt * 8 + tig * 2;
            const float b0 = bias[n], b1 = bias[n + 1];
            #pragma unroll
            for (int half_ = 0; half_ < 2; half_++) {
                const int m = blockIdx.y * 128 + wm * 64 + mt * 16 + gid + half_ * 8;
                float2 v;
                v.x = acc[mt][nt][half_ * 2 + 0] + b0;
                v.y = acc[mt][nt][half_ * 2 + 1] + b1;
                *(float2*)(C + (size_t)m * (gridDim.x * 128) + n) = v;
            }
        }
    }
}

// =================== split-fp16 (3xMMA k16) GEMM + ReLU for mask MLP =======
__global__ __launch_bounds__(256)
void hgemm_3x_relu(const float* __restrict__ A, const float* __restrict__ W,
                   const float* __restrict__ bias, float* __restrict__ C, int K)
{
    extern __shared__ __align__(16) char smemraw[];
    uint32_t* sw = (uint32_t*)smemraw;
    const uint32_t sbase = smem_u32(sw);
    const float* swf = (const float*)sw;
    const int tid  = threadIdx.x;
    const int wid  = tid >> 5;
    const int lane = tid & 31;
    const int gid  = lane >> 2;
    const int tig  = lane & 3;
    const int wm   = wid >> 2;
    const int wn   = wid & 3;

    const float* Ag = A + (size_t)blockIdx.y * 128 * K;
    const float* Wg = W + (size_t)blockIdx.x * 128 * K;

    float acc[4][4][4];
    #pragma unroll
    for (int i = 0; i < 4; i++)
        #pragma unroll
        for (int j = 0; j < 4; j++)
            #pragma unroll
            for (int f = 0; f < 4; f++) acc[i][j][f] = 0.f;

    const int NC = K >> 5;
    const int r0 = tid >> 3;
    const int sg = tid & 7;

    {
        const uint32_t ab = sbase, wb = sbase + 4608u * 4u;
        #pragma unroll
        for (int i = 0; i < 4; i++) {
            const int row = r0 + i * 32;
            const uint32_t off = (uint32_t)(row * 36 + sg * 4) * 4u;
            cp16(ab + off, Ag + (size_t)row * K + sg * 4);
            cp16(wb + off, Wg + (size_t)row * K + sg * 4);
        }
        asm volatile("cp.async.commit_group;" ::: "memory");
    }

    for (int c = 0; c < NC; c++) {
        if (c + 1 < NC) {
            const uint32_t st = (uint32_t)((c + 1) & 1) * 9216u * 4u;
            const uint32_t ab = sbase + st, wb = sbase + st + 4608u * 4u;
            const int kn = (c + 1) << 5;
            #pragma unroll
            for (int i = 0; i < 4; i++) {
                const int row = r0 + i * 32;
                const uint32_t off = (uint32_t)(row * 36 + sg * 4) * 4u;
                cp16(ab + off, Ag + (size_t)row * K + kn + sg * 4);
                cp16(wb + off, Wg + (size_t)row * K + kn + sg * 4);
            }
            asm volatile("cp.async.commit_group;" ::: "memory");
            asm volatile("cp.async.wait_group 1;" ::: "memory");
        } else {
            asm volatile("cp.async.wait_group 0;" ::: "memory");
        }
        __syncthreads();

        const float* As = swf + (c & 1) * 9216;
        const float* Ws = As + 4608;
        #pragma unroll
        for (int ks = 0; ks < 2; ks++) {
            const int k0 = ks * 16;
            uint32_t ah[4][4], al[4][4];
            #pragma unroll
            for (int mt = 0; mt < 4; mt++) {
                const int r = wm * 64 + mt * 16 + gid;
                float2 p0 = *(const float2*)&As[ r      * 36 + k0 + 2*tig    ];
                float2 p1 = *(const float2*)&As[(r + 8) * 36 + k0 + 2*tig    ];
                float2 p2 = *(const float2*)&As[ r      * 36 + k0 + 2*tig + 8];
                float2 p3 = *(const float2*)&As[(r + 8) * 36 + k0 + 2*tig + 8];
                split_h2(p0.x, p0.y, ah[mt][0], al[mt][0]);
                split_h2(p1.x, p1.y, ah[mt][1], al[mt][1]);
                split_h2(p2.x, p2.y, ah[mt][2], al[mt][2]);
                split_h2(p3.x, p3.y, ah[mt][3], al[mt][3]);
            }
            uint32_t bh_[4][2], bl_[4][2];
            #pragma unroll
            for (int nt = 0; nt < 4; nt++) {
                const int n = wn * 32 + nt * 8 + gid;
                float2 q0 = *(const float2*)&Ws[n * 36 + k0 + 2*tig    ];
                float2 q1 = *(const float2*)&Ws[n * 36 + k0 + 2*tig + 8];
                split_h2(q0.x, q0.y, bh_[nt][0], bl_[nt][0]);
                split_h2(q1.x, q1.y, bh_[nt][1], bl_[nt][1]);
            }
            #pragma unroll
            for (int mt = 0; mt < 4; mt++)
                #pragma unroll
                for (int nt = 0; nt < 4; nt++) {
                    mma_f16(acc[mt][nt], al[mt], bh_[nt]);
                    mma_f16(acc[mt][nt], ah[mt], bl_[nt]);
                    mma_f16(acc[mt][nt], ah[mt], bh_[nt]);
                }
        }
        __syncthreads();
    }

    #pragma unroll
    for (int mt = 0; mt < 4; mt++) {
        #pragma unroll
        for (int nt = 0; nt < 4; nt++) {
            const int n = blockIdx.x * 128 + wn * 32 + nt * 8 + tig * 2;
            const float b0 = bias[n], b1 = bias[n + 1];
            #pragma unroll
            for (int half_ = 0; half_ < 2; half_++) {
                const int m = blockIdx.y * 128 + wm * 64 + mt * 16 + gid + half_ * 8;
                float2 v;
                v.x = fmaxf(acc[mt][nt][half_ * 2 + 0] + b0, 0.f);
                v.y = fmaxf(acc[mt][nt][half_ * 2 + 1] + b1, 0.f);
                *(float2*)(C + (size_t)m * (gridDim.x * 128) + n) = v;
            }
        }
    }
}

// =================== fp16 flash attention with ldmatrix (R15-verified) =====
// Q,K fp16 (B,H,S,D); V fp16 transposed (B,H,D,S). exp2 softmax.
// smem: 2 stages x (K 64x72 + Vt 64x72 halves) = 36864 B.
__global__ __launch_bounds__(256, 2)
void flash_h(const __half* __restrict__ Q, const __half* __restrict__ Kg,
             const __half* __restrict__ Vg, const float* __restrict__ gate,
             __half* __restrict__ ctx)
{
    extern __shared__ __align__(16) char smemraw[];
    __half* swh = (__half*)smemraw;
    const uint32_t sbase = smem_u32(swh);
    const int tid  = threadIdx.x;
    const int wid  = tid >> 5;
    const int lane = tid & 31;
    const int gid  = lane >> 2;
    const int tig  = lane & 3;
    const int bh   = blockIdx.y;
    const int b    = bh >> 4, h = bh & 15;
    const int q0   = blockIdx.x * 128;

    const __half* Qt = Q  + ((size_t)bh * S_LEN + q0) * HD;
    const __half* Kb = Kg + (size_t)bh * S_LEN * HD;
    const __half* Vb = Vg + (size_t)bh * HD * S_LEN;

    const int a23 = lane >> 3, rin = lane & 7;
    const uint32_t alane = (uint32_t)((((a23 & 1) * 8 + rin) * 72 + (a23 >> 1) * 8) * 2);
    const uint32_t blane = (uint32_t)((((a23 >> 1) * 8 + rin) * 72 + (a23 & 1) * 8) * 2);

    #pragma unroll
    for (int i = 0; i < 4; i++) {
        const int fi = tid + i * 256;
        const int r = fi >> 3, seg = fi & 7;
        uint4 v = *(const uint4*)(Qt + r * 64 + seg * 8);
        *(uint4*)(swh + r * 72 + seg * 8) = v;
    }
    __syncthreads();
    uint32_t qa[4][4];
    {
        const uint32_t qaddr = sbase + (uint32_t)(wid * 16) * 144u + alane;
        #pragma unroll
        for (int ks = 0; ks < 4; ks++)
            ldsm4(qa[ks], qaddr + (uint32_t)(ks * 32));
    }
    __syncthreads();

    #pragma unroll 1
    for (int t = 0; t < 2; t++) {
        const uint32_t kb = sbase + (uint32_t)t * 18432u;
        const uint32_t vb = kb + 9216u;
        const __half* Ksrc = Kb + (size_t)t * 64 * 64;
        const __half* Vsrc = Vb + (size_t)t * 64;
        #pragma unroll
        for (int i = 0; i < 4; i++) {
            const int fi = tid + i * 256;
            const int half_sel = fi >> 9;
            const int j = fi & 511;
            const int r = j >> 3, seg = j & 7;
            if (half_sel == 0)
                cp16(kb + (uint32_t)(r * 72 + seg * 8) * 2u, Ksrc + r * 64 + seg * 8);
            else
                cp16(vb + (uint32_t)(r * 72 + seg * 8) * 2u, Vsrc + (size_t)r * S_LEN + seg * 8);
        }
        asm volatile("cp.async.commit_group;" ::: "memory");
    }

    float miA = -INFINITY, miB = -INFINITY, liA = 0.f, liB = 0.f;
    float oa[8][4];
    #pragma unroll
    for (int nt = 0; nt < 8; nt++)
        #pragma unroll
        for (int f = 0; f < 4; f++) oa[nt][f] = 0.f;

    const int NT = S_LEN / 64;
    for (int t = 0; t < NT; t++) {
        if (t < NT - 2) asm volatile("cp.async.wait_group 1;" ::: "memory");
        else            asm volatile("cp.async.wait_group 0;" ::: "memory");
        __syncthreads();
        const uint32_t ksAddr = sbase + (uint32_t)(t & 1) * 18432u + blane;
        const uint32_t vsAddr = ksAddr + 9216u;

        float sa[8][4];
        #pragma unroll
        for (int nt = 0; nt < 8; nt++)
            #pragma unroll
            for (int f = 0; f < 4; f++) sa[nt][f] = 0.f;
        #pragma unroll
        for (int ks = 0; ks < 4; ks++) {
            #pragma unroll
            for (int ntp = 0; ntp < 4; ntp++) {
                uint32_t b4[4];
                ldsm4(b4, ksAddr + (uint32_t)(ntp * 2304 + ks * 32));
                mma_f16(sa[2*ntp    ], qa[ks], &b4[0]);
                mma_f16(sa[2*ntp + 1], qa[ks], &b4[2]);
            }
        }

        float rmA = -INFINITY, rmB = -INFINITY;
        #pragma unroll
        for (int nt = 0; nt < 8; nt++) {
            rmA = fmaxf(rmA, fmaxf(sa[nt][0], sa[nt][1]));
            rmB = fmaxf(rmB, fmaxf(sa[nt][2], sa[nt][3]));
        }
        rmA = fmaxf(rmA, __shfl_xor_sync(0xffffffffu, rmA, 1));
        rmA = fmaxf(rmA, __shfl_xor_sync(0xffffffffu, rmA, 2));
        rmB = fmaxf(rmB, __shfl_xor_sync(0xffffffffu, rmB, 1));
        rmB = fmaxf(rmB, __shfl_xor_sync(0xffffffffu, rmB, 2));

        const float mAn = fmaxf(miA, rmA);
        const float mBn = fmaxf(miB, rmB);
        const float aA  = exp2f(miA - mAn);
        const float aB  = exp2f(miB - mBn);
        miA = mAn; miB = mBn;

        float rsA = 0.f, rsB = 0.f;
        #pragma unroll
        for (int nt = 0; nt < 8; nt++) {
            sa[nt][0] = exp2f(sa[nt][0] - mAn);
            sa[nt][1] = exp2f(sa[nt][1] - mAn);
            sa[nt][2] = exp2f(sa[nt][2] - mBn);
            sa[nt][3] = exp2f(sa[nt][3] - mBn);
            rsA += sa[nt][0] + sa[nt][1];
            rsB += sa[nt][2] + sa[nt][3];
        }
        rsA += __shfl_xor_sync(0xffffffffu, rsA, 1);
        rsA += __shfl_xor_sync(0xffffffffu, rsA, 2);
        rsB += __shfl_xor_sync(0xffffffffu, rsB, 1);
        rsB += __shfl_xor_sync(0xffffffffu, rsB, 2);
        liA = liA * aA + rsA;
        liB = liB * aB + rsB;
        #pragma unroll
        for (int nt = 0; nt < 8; nt++) {
            oa[nt][0] *= aA; oa[nt][1] *= aA;
            oa[nt][2] *= aB; oa[nt][3] *= aB;
        }

        #pragma unroll
        for (int kk = 0; kk < 4; kk++) {
            uint32_t af[4];
            af[0] = h2u(__floats2half2_rn(sa[2*kk  ][0], sa[2*kk  ][1]));
            af[1] = h2u(__floats2half2_rn(sa[2*kk  ][2], sa[2*kk  ][3]));
            af[2] = h2u(__floats2half2_rn(sa[2*kk+1][0], sa[2*kk+1][1]));
            af[3] = h2u(__floats2half2_rn(sa[2*kk+1][2], sa[2*kk+1][3]));
            #pragma unroll
            for (int ntp = 0; ntp < 4; ntp++) {
                uint32_t b4[4];
                ldsm4(b4, vsAddr + (uint32_t)(ntp * 2304 + kk * 32));
                mma_f16(oa[2*ntp    ], af, &b4[0]);
                mma_f16(oa[2*ntp + 1], af, &b4[2]);
            }
        }
        __syncthreads();

        if (t + 2 < NT) {
            const uint32_t kb = sbase + (uint32_t)(t & 1) * 18432u;
            const uint32_t vb = kb + 9216u;
            const __half* Ksrc = Kb + (size_t)(t + 2) * 64 * 64;
            const __half* Vsrc = Vb + (size_t)(t + 2) * 64;
            #pragma unroll
            for (int i = 0; i < 4; i++) {
                const int fi = tid + i * 256;
                const int half_sel = fi >> 9;
                const int j = fi & 511;
                const int r = j >> 3, seg = j & 7;
                if (half_sel == 0)
                    cp16(kb + (uint32_t)(r * 72 + seg * 8) * 2u, Ksrc + r * 64 + seg * 8);
                else
                    cp16(vb + (uint32_t)(r * 72 + seg * 8) * 2u, Vsrc + (size_t)r * S_LEN + seg * 8);
            }
            asm volatile("cp.async.commit_group;" ::: "memory");
        }
    }

    const int sA = q0 + wid * 16 + gid;
    const int sB = sA + 8;
    const float gA = gate[(size_t)bh * S_LEN + sA];
    const float gB = gate[(size_t)bh * S_LEN + sB];
    const float invA = gA / liA;
    const float invB = gB / liB;
    #pragma unroll
    for (int nt = 0; nt < 8; nt++) {
        const int col = h * 64 + nt * 8 + tig * 2;
        __half2 va = __floats2half2_rn(oa[nt][0] * invA, oa[nt][1] * invA);
        __half2 vb = __floats2half2_rn(oa[nt][2] * invB, oa[nt][3] * invB);
        *(uint32_t*)(ctx + ((size_t)sA * BATCH + b) * EMB + col) = h2u(va);
        *(uint32_t*)(ctx + ((size_t)sB * BATCH + b) * EMB + col) = h2u(vb);
    }
}

// ---------------- fold head_sig into inf2 ---------------------------------
__global__ void combine_sig(const float* __restrict__ hs,
                            const float* __restrict__ w2,
                            const float* __restrict__ b2,
                            float* __restrict__ mcomb,
                            float* __restrict__ cbias)
{
    const int idx = blockIdx.x * blockDim.x + threadIdx.x;
    if (idx < NH * HID) {
        const int h = idx / HID, k = idx % HID;
        float a = 0.f;
        #pragma unroll
        for (int j = 0; j < 64; j++) a += hs[h*64 + j] * w2[j*HID + k];
        mcomb[idx] = a;
    }
    if (idx < NH) {
        float a = 0.f;
        #pragma unroll
        for (int j = 0; j < 64; j++) a += hs[idx*64 + j] * b2[j];
        cbias[idx] = a;
    }
}

// ---------------- head scores + top-12 mask (float4 loads) ----------------
__global__ __launch_bounds__(256)
void head_scores(const float* __restrict__ t1, const float* __restrict__ mcomb,
                 const float* __restrict__ cbias, float* __restrict__ mask)
{
    const int warp = (blockIdx.x * blockDim.x + threadIdx.x) >> 5;
    const int lane = threadIdx.x & 31;
    if (warp >= MROWS) return;
    const float4* row4 = (const float4*)(t1 + (size_t)warp * HID);
    const float4* mc4  = (const float4*)mcomb;

    float acc[NH];
    #pragma unroll
    for (int h = 0; h < NH; h++) acc[h] = 0.f;
    #pragma unroll
    for (int it = 0; it < 4; it++) {
        const int k4 = it * 32 + lane;
        const float4 a = row4[k4];
        #pragma unroll
        for (int h = 0; h < NH; h++) {
            const float4 m = mc4[h * (HID/4) + k4];
            acc[h] += a.x*m.x + a.y*m.y + a.z*m.z + a.w*m.w;
        }
    }
    #pragma unroll
    for (int h = 0; h < NH; h++)
        #pragma unroll
        for (int off = 16; off > 0; off >>= 1)
            acc[h] += __shfl_xor_sync(0xffffffffu, acc[h], off);

    if (lane == 0) {
        float sc[NH], tmp[NH];
        #pragma unroll
        for (int h = 0; h < NH; h++) { sc[h] = acc[h] + cbias[h]; tmp[h] = sc[h]; }
        float thr = 0.f;
        for (int it = 0; it < NH - 4; it++) {
            int bi = 0; float bv = tmp[0];
            #pragma unroll
            for (int h = 1; h < NH; h++) if (tmp[h] > bv) { bv = tmp[h]; bi = h; }
            thr = bv; tmp[bi] = -INFINITY;
        }
        const int s = warp >> 1, b = warp & 1;
        #pragma unroll
        for (int h = 0; h < NH; h++)
            mask[((size_t)(b * NH + h)) * S_LEN + s] = (sc[h] >= thr) ? 1.f : 0.f;
    }
}

// ---------------------------------------------------------------------------
extern "C" void kernel_launch(void* const* d_in, const int* in_sizes, int n_in,
                              void* d_out, int out_size)
{
    const float* query   = (const float*)d_in[0];
    const float* q_w     = (const float*)d_in[1];
    const float* q_b     = (const float*)d_in[2];
    const float* k_w     = (const float*)d_in[3];
    const float* k_b     = (const float*)d_in[4];
    const float* v_w     = (const float*)d_in[5];
    const float* v_b     = (const float*)d_in[6];
    const float* out_w   = (const float*)d_in[7];
    const float* out_b   = (const float*)d_in[8];
    const float* inf1_w  = (const float*)d_in[9];
    const float* inf1_b  = (const float*)d_in[10];
    const float* inf2_w  = (const float*)d_in[11];
    const float* inf2_b  = (const float*)d_in[12];
    const float* head_sig= (const float*)d_in[13];
    float* out = (float*)d_out;

    __half *pqkv, *pctx, *pqh, *pwqkv, *pwo;
    float *pt1, *pmc, *pcb, *pmask;
    cudaGetSymbolAddress((void**)&pqkv, g_qkv);
    cudaGetSymbolAddress((void**)&pctx, g_ctx);
    cudaGetSymbolAddress((void**)&pt1,  g_t1);
    cudaGetSymbolAddress((void**)&pmc,  g_mcomb);
    cudaGetSymbolAddress((void**)&pcb,  g_cbias);
    cudaGetSymbolAddress((void**)&pmask,g_mask);
    cudaGetSymbolAddress((void**)&pqh,  g_qh);
    cudaGetSymbolAddress((void**)&pwqkv,g_wqkv);
    cudaGetSymbolAddress((void**)&pwo,  g_wo);

    const int HGS = 73728;   // fp16 GEMM: 2 stages x 18432 halves
    const int GS3 = 73728;   // mask MLP fp32 stage layout
    const int FS  = 36864;   // flash fp16: 2 stages
    cudaFuncSetAttribute(hgemm_qkv, cudaFuncAttributeMaxDynamicSharedMemorySize, HGS);
    cudaFuncSetAttribute(hgemm_out, cudaFuncAttributeMaxDynamicSharedMemorySize, HGS);
    cudaFuncSetAttribute(hgemm_3x_relu, cudaFuncAttributeMaxDynamicSharedMemorySize, GS3);
    cudaFuncSetAttribute(flash_h, cudaFuncAttributeMaxDynamicSharedMemorySize, FS);

    // side stream + fork/join events (created per call; never destroyed so
    // the captured graph's references stay valid)
    cudaStream_t s2;
    cudaEvent_t eFork, eJoin;
    cudaStreamCreateWithFlags(&s2, cudaStreamNonBlocking);
    cudaEventCreateWithFlags(&eFork, cudaEventDisableTiming);
    cudaEventCreateWithFlags(&eJoin, cudaEventDisableTiming);

    cudaEventRecord(eFork, 0);
    cudaStreamWaitEvent(s2, eFork, 0);

    // --- side stream: wo convert -> combine_sig -> MLP -> head_scores ------
    round_wo<<<(NW4 + 255)/256, 256, 0, s2>>>(out_w, pwo);
    combine_sig<<<(NH*HID + 255)/256, 256, 0, s2>>>(head_sig, inf2_w, inf2_b,
                                                    pmc, pcb);
    {
        dim3 g(HID/128, MROWS/128);
        hgemm_3x_relu<<<g, 256, GS3, s2>>>(query, inf1_w, inf1_b, pt1, EMB);
    }
    head_scores<<<MROWS/8, 256, 0, s2>>>(pt1, pmc, pcb, pmask);
    cudaEventRecord(eJoin, s2);

    // --- main stream: fp16 convert (query + qkv weights) -> QKV -------------
    {
        const int total = NQ4 + 3 * NW4;
        round_main<<<(total + 255)/256, 256>>>(query, q_w, k_w, v_w, pqh, pwqkv);
    }
    {
        dim3 g(EMB/128, MROWS/128, 3);
        hgemm_qkv<<<g, 256, HGS>>>(pqh, pwqkv, q_b, k_b, v_b, pqkv, EMB);
    }

    cudaStreamWaitEvent(0, eJoin, 0);

    // --- flash attention (fp16, ldmatrix, 2-stage) -> ctx fp16 --------------
    {
        dim3 g(S_LEN/128, BATCH*NH);
        flash_h<<<g, 256, FS>>>(pqkv, pqkv + HSZ, pqkv + 2*HSZ, pmask, pctx);
    }
    // --- output projection ---------------------------------------------------
    {
        dim3 g(EMB/128, MROWS/128);
        hgemm_out<<<g, 256, HGS>>>(pctx, pwo, out_b, out, EMB);
    }
    (void)in_sizes; (void)n_in; (void)out_size;
}